// round 7
// baseline (speedup 1.0000x reference)
#include <cuda_runtime.h>
#include <cuda_fp16.h>
#include <math.h>
#include <stdint.h>

#define LL 160
#define BB 16
#define EE 512
#define CC 256
#define HH 512
#define DM 128
#define DO 512
#define TOK (BB*LL)
#define CP 258
#define W1C 1028
#define KC (3*EE)            /* 1536 */
#define SPB 18
#define GRID_PAIRS (BB*SPB)  /* 288 */
#define NKT (KC/16)          /* 96 */

__device__ __half g_whfrag[NKT*32*32*4];
__device__ float g_W1T[CP*256];
__device__ float g_y[TOK*CC];
__device__ float g_ssum[40*256];
__device__ float g_ssq[40*256];
__device__ float g_scale[CC];
__device__ float g_shift[CC];
__device__ float g_u[TOK*DM];
__device__ float g_v[TOK*DM];
__device__ float g_hw[BB*DM];
__device__ float g_part[BB*SPB*DM];

__device__ __forceinline__ float lrelu(float x){ return x > 0.f ? x : 0.1f*x; }

__device__ __forceinline__ uint32_t h2pack(float lo, float hi){
    __half2 h = __floats2half2_rn(lo, hi);
    return *(uint32_t*)&h;
}
__device__ __forceinline__ void mma_f16(float& d0, float& d1, float& d2, float& d3,
                                        uint32_t a0, uint32_t a1, uint32_t a2, uint32_t a3,
                                        uint32_t b0, uint32_t b1){
    asm volatile("mma.sync.aligned.m16n8k16.row.col.f32.f16.f16.f32 "
                 "{%0,%1,%2,%3},{%4,%5,%6,%7},{%8,%9},{%0,%1,%2,%3};"
                 : "+f"(d0), "+f"(d1), "+f"(d2), "+f"(d3)
                 : "r"(a0), "r"(a1), "r"(a2), "r"(a3), "r"(b0), "r"(b1));
}

/* ---------------- prep ---------------- */
__global__ void k_prep(const float* __restrict__ conv_w, const float* __restrict__ W1){
    int idx = blockIdx.x*256 + threadIdx.x;
    if (idx < KC*CC){
        int k = idx >> 8, n = idx & 255;
        int e = k & 511, kk = k >> 9;
        float v = conv_w[n*KC + e*3 + kk];
        int kt = k >> 4, r = k & 15;
        int nt = n >> 3, gg = n & 7, c = (r & 7) >> 1;
        int lane = gg*4 + c;
        int hs = ((r >> 3) << 1) | (r & 1);
        g_whfrag[(((kt*32 + nt)*32 + lane) << 2) + hs] = __float2half(v);
    }
    if (idx < CP*256){
        int k = idx >> 8, n = idx & 255;
        g_W1T[idx] = (n < DM) ? W1[n*W1C + k] : W1[(n-DM)*W1C + CP + k];
    }
}

__global__ void k_hw(const float* __restrict__ h, const float* __restrict__ W1){
    __shared__ float hs[HH];
    int b = blockIdx.x, tid = threadIdx.x;
    for (int i = tid; i < HH; i += 128) hs[i] = h[b*HH + i];
    __syncthreads();
    float acc = 0.f;
    const float* w = W1 + tid*W1C + 2*CP;
    #pragma unroll 8
    for (int c = 0; c < HH; c++) acc += hs[c]*w[c];
    g_hw[b*DM + tid] = acc;
}

/* ---------------- conv1d as fp16 mma GEMM (known-good) ---------------- */
__global__ void __launch_bounds__(256,1) k_conv(const float* __restrict__ x,
                                                const float* __restrict__ conv_b){
    __shared__ uint32_t xh32[18*260];
    __shared__ uint2 wfr[3*32*32];
    int l0 = blockIdx.x*16, b = blockIdx.y;
    int tid = threadIdx.x, w = tid >> 5, t = tid & 31;
    int g = t >> 2, c = t & 3;

    for (int idx = tid; idx < 18*256; idx += 256){
        int r = idx >> 8, i = idx & 255;
        int l = l0 + r - 1;
        uint32_t pv = 0u;
        if (l >= 0 && l < LL){
            const float2 xv = *(const float2*)(x + (l*BB + b)*EE + 2*i);
            pv = h2pack(xv.x, xv.y);
        }
        xh32[r*260 + i] = pv;
    }

    float d[4][4];
    #pragma unroll
    for (int j = 0; j < 4; j++){ d[j][0]=0.f; d[j][1]=0.f; d[j][2]=0.f; d[j][3]=0.f; }

    const uint2* gsrc = (const uint2*)g_whfrag;
    for (int cc = 0; cc < 32; cc++){
        __syncthreads();
        const uint2* src = gsrc + cc*3072;
        #pragma unroll
        for (int q = 0; q < 12; q++) wfr[tid + q*256] = src[tid + q*256];
        __syncthreads();
        #pragma unroll
        for (int kt = 0; kt < 3; kt++){
            int k = cc*48 + kt*16;
            int kk = k >> 9, e2 = (k & 511) >> 1;
            const uint32_t* r0 = xh32 + (g + kk)*260 + e2 + c;
            const uint32_t* r1 = xh32 + (g + 8 + kk)*260 + e2 + c;
            uint32_t a0 = r0[0], a1 = r1[0], a2 = r0[4], a3 = r1[4];
            const uint2* wk = wfr + (kt*32 + w*4)*32 + t;
            #pragma unroll
            for (int j = 0; j < 4; j++){
                uint2 bb = wk[j*32];
                mma_f16(d[j][0], d[j][1], d[j][2], d[j][3], a0, a1, a2, a3, bb.x, bb.y);
            }
        }
    }
    #pragma unroll
    for (int j = 0; j < 4; j++){
        int n = w*32 + j*8 + 2*c;
        float bx = conv_b[n], by = conv_b[n+1];
        int trow = (b*LL + l0 + g)*CC;
        g_y[trow + n]             = lrelu(d[j][0] + bx);
        g_y[trow + n + 1]         = lrelu(d[j][1] + by);
        g_y[trow + 8*CC + n]      = lrelu(d[j][2] + bx);
        g_y[trow + 8*CC + n + 1]  = lrelu(d[j][3] + by);
    }
}

/* BN stats: coalesced partials (40 blocks x 64 tokens) + finalize */
__global__ void k_stats_part(){
    int blk = blockIdx.x, tid = threadIdx.x;
    int t0 = blk*64;
    float a = 0.f, q = 0.f;
    for (int tt = 0; tt < 64; tt++){
        float v = g_y[(t0 + tt)*CC + tid];
        a += v; q += v*v;
    }
    g_ssum[blk*256 + tid] = a;
    g_ssq[blk*256 + tid]  = q;
}
__global__ void k_stats_fin(const float* __restrict__ bn_g, const float* __restrict__ bn_b){
    int c = threadIdx.x;
    float a = 0.f, q = 0.f;
    #pragma unroll
    for (int blk = 0; blk < 40; blk++){
        a += g_ssum[blk*256 + c];
        q += g_ssq[blk*256 + c];
    }
    float mu = a/(float)TOK;
    float var = q/(float)TOK - mu*mu;
    float sc = bn_g[c]*rsqrtf(var + 1e-5f);
    g_scale[c] = sc;
    g_shift[c] = bn_b[c] - mu*sc;
}

__global__ void __launch_bounds__(256,4) k_uv(){
    __shared__ float xf[8*260];
    int t0 = blockIdx.x*8;
    int b = t0 / LL;
    int tid = threadIdx.x;
    for (int idx = tid; idx < 8*CC; idx += 256){
        int tok = idx >> 8, c = idx & 255;
        xf[tok*260 + c] = g_y[(t0+tok)*CC + c]*g_scale[c] + g_shift[c];
    }
    if (tid < 16){
        int tok = tid >> 1;
        float fi = (float)(t0 + tok - b*LL);
        float sL = sqrtf(160.f);
        float cv = (tid & 1) ? (fmodf(fi, sL) - 2.f)*0.5f : (fi/sL - 2.f)*0.5f;
        xf[tok*260 + 256 + (tid & 1)] = cv;
    }
    __syncthreads();
    int n = tid;
    float acc[8];
    #pragma unroll
    for (int i = 0; i < 8; i++) acc[i] = 0.f;
    #pragma unroll 2
    for (int k = 0; k < CP; k++){
        float w = g_W1T[k*256 + n];
        #pragma unroll
        for (int tok = 0; tok < 8; tok++) acc[tok] += xf[tok*260 + k]*w;
    }
    if (n < DM){
        #pragma unroll
        for (int tok = 0; tok < 8; tok++) g_u[(t0+tok)*DM + n] = acc[tok];
    } else {
        float hw = g_hw[b*DM + n - DM];
        #pragma unroll
        for (int tok = 0; tok < 8; tok++) g_v[(t0+tok)*DM + n - DM] = acc[tok] + hw;
    }
}

/* ---------------- pair MLP, now 2 CTAs/SM ----------------
   part_s ALIASES u_s (used only after the tile loop, fenced by syncthreads) */
#define SM_U     24576
#define SM_V     (SM_U + 16*132)
#define SM_B1    (SM_V + 8*132)
#define SM_BIAS  (SM_B1 + 128)
#define SM_TOTF  (SM_BIAS + 384)
#define DYN_SMEM (SM_TOTF*4)

__global__ void __launch_bounds__(256,2) k_pairs_mma(
        const float* __restrict__ W2, const float* __restrict__ W3, const float* __restrict__ W4,
        const float* __restrict__ b1, const float* __restrict__ b2,
        const float* __restrict__ b3, const float* __restrict__ b4){
    extern __shared__ float smf[];
    float* u_s    = smf + SM_U;
    float* v_s    = smf + SM_V;
    float* b1_s   = smf + SM_B1;
    float* bias_s = smf + SM_BIAS;
    float* part_s = smf + SM_U;      /* alias: live only after the tile loop */
    uint2* wfrag  = (uint2*)smf;

    int tid = threadIdx.x, w = tid >> 5, t = tid & 31;
    int g = t >> 2, c = t & 3;

    for (int l = 0; l < 3; l++){
        const float* W = (l == 0) ? W2 : (l == 1) ? W3 : W4;
        for (int idx = tid; idx < 4096; idx += 256){
            int lane = idx & 31, nt = (idx >> 5) & 15, kt = idx >> 9;
            int gg = lane >> 2, cc = lane & 3;
            const float* Wr = W + (nt*8 + gg)*DM + kt*16 + 2*cc;
            uint2 fr;
            fr.x = h2pack(Wr[0], Wr[1]);
            fr.y = h2pack(Wr[8], Wr[9]);
            wfrag[l*4096 + idx] = fr;
        }
    }
    for (int i = tid; i < 128; i += 256){
        b1_s[i]          = b1[i];
        bias_s[i]        = b2[i];
        bias_s[128 + i]  = b3[i];
        bias_s[256 + i]  = b4[i];
    }

    int cta = blockIdx.x;
    int b = cta / SPB, s = cta % SPB;
    int t0 = s*11 + (s < 2 ? s : 2);
    int t1 = t0 + 11 + (s < 2 ? 1 : 0);

    uint32_t a[8][4];
    float    d[16][4];
    float    acc32[16][2];
    #pragma unroll
    for (int nt = 0; nt < 16; nt++){ acc32[nt][0] = 0.f; acc32[nt][1] = 0.f; }

    for (int tt = t0; tt < t1; tt++){
        int lt0 = (tt / 10)*8, m0 = (tt % 10)*16;
        __syncthreads();
        for (int idx = tid; idx < 16*DM; idx += 256){
            int mi = idx >> 7, k = idx & 127;
            u_s[mi*132 + k] = g_u[(b*LL + m0 + mi)*DM + k];
        }
        for (int idx = tid; idx < 8*DM; idx += 256){
            int li = idx >> 7, k = idx & 127;
            v_s[li*132 + k] = g_v[(b*LL + lt0 + li)*DM + k];
        }
        __syncthreads();

        #pragma unroll
        for (int kt = 0; kt < 8; kt++){
            int k = kt*16 + 2*c;
            const float* vr = v_s + w*132 + k;
            const float* br = b1_s + k;
            float vb0 = vr[0] + br[0], vb1 = vr[1] + br[1];
            float vb8 = vr[8] + br[8], vb9 = vr[9] + br[9];
            const float* ug  = u_s + g*132 + k;
            const float* uh  = u_s + (g+8)*132 + k;
            a[kt][0] = h2pack(lrelu(ug[0] + vb0), lrelu(ug[1] + vb1));
            a[kt][1] = h2pack(lrelu(uh[0] + vb0), lrelu(uh[1] + vb1));
            a[kt][2] = h2pack(lrelu(ug[8] + vb8), lrelu(ug[9] + vb9));
            a[kt][3] = h2pack(lrelu(uh[8] + vb8), lrelu(uh[9] + vb9));
        }

        #pragma unroll 1
        for (int l = 0; l < 3; l++){
            #pragma unroll
            for (int nt = 0; nt < 16; nt++){
                d[nt][0] = 0.f; d[nt][1] = 0.f; d[nt][2] = 0.f; d[nt][3] = 0.f;
            }
            const uint2* wl = wfrag + l*4096 + t;
            #pragma unroll
            for (int kt = 0; kt < 8; kt++){
                const uint2* wk = wl + kt*512;
                #pragma unroll
                for (int nt = 0; nt < 16; nt++){
                    uint2 bb = wk[nt*32];
                    mma_f16(d[nt][0], d[nt][1], d[nt][2], d[nt][3],
                            a[kt][0], a[kt][1], a[kt][2], a[kt][3], bb.x, bb.y);
                }
            }
            if (l < 2){
                const float* bl = bias_s + l*128;
                #pragma unroll
                for (int kt = 0; kt < 8; kt++){
                    float bx0 = bl[kt*16 + 2*c],     by0 = bl[kt*16 + 2*c + 1];
                    float bx8 = bl[kt*16 + 2*c + 8], by8 = bl[kt*16 + 2*c + 9];
                    a[kt][0] = h2pack(lrelu(d[2*kt][0]   + bx0), lrelu(d[2*kt][1]   + by0));
                    a[kt][1] = h2pack(lrelu(d[2*kt][2]   + bx0), lrelu(d[2*kt][3]   + by0));
                    a[kt][2] = h2pack(lrelu(d[2*kt+1][0] + bx8), lrelu(d[2*kt+1][1] + by8));
                    a[kt][3] = h2pack(lrelu(d[2*kt+1][2] + bx8), lrelu(d[2*kt+1][3] + by8));
                }
            } else {
                const float* bl = bias_s + 256;
                #pragma unroll
                for (int nt = 0; nt < 16; nt++){
                    float bx = bl[nt*8 + 2*c], by = bl[nt*8 + 2*c + 1];
                    acc32[nt][0] += lrelu(d[nt][0] + bx) + lrelu(d[nt][2] + bx);
                    acc32[nt][1] += lrelu(d[nt][1] + by) + lrelu(d[nt][3] + by);
                }
            }
        }
    }

    __syncthreads();   /* fence before part_s aliases u_s */

    #pragma unroll
    for (int nt = 0; nt < 16; nt++){
        #pragma unroll
        for (int r = 0; r < 2; r++){
            float v = acc32[nt][r];
            v += __shfl_xor_sync(0xffffffffu, v, 4);
            v += __shfl_xor_sync(0xffffffffu, v, 8);
            v += __shfl_xor_sync(0xffffffffu, v, 16);
            acc32[nt][r] = v;
        }
    }
    if (g == 0){
        #pragma unroll
        for (int nt = 0; nt < 16; nt++){
            part_s[w*128 + nt*8 + 2*c]     = acc32[nt][0];
            part_s[w*128 + nt*8 + 2*c + 1] = acc32[nt][1];
        }
    }
    __syncthreads();
    if (tid < 128){
        float r = 0.f;
        #pragma unroll
        for (int ww = 0; ww < 8; ww++) r += part_s[ww*128 + tid];
        g_part[(b*SPB + s)*DM + tid] = r;
    }
}

/* final reduction + 2-layer head */
__global__ void k_tail(const float* __restrict__ W5, const float* __restrict__ b5,
                       const float* __restrict__ W6, const float* __restrict__ b6,
                       float* __restrict__ out){
    __shared__ float s_s[DM], s5[DM];
    int b = blockIdx.x, tid = threadIdx.x;
    if (tid < DM){
        float a = 0.f;
        #pragma unroll
        for (int t = 0; t < SPB; t++) a += g_part[(b*SPB + t)*DM + tid];
        s_s[tid] = a;
    }
    __syncthreads();
    if (tid < DM){
        float a = 0.f;
        const float* w = W5 + tid*DM;
        #pragma unroll 8
        for (int k = 0; k < DM; k++) a += s_s[k]*w[k];
        s5[tid] = lrelu(a + b5[tid]);
    }
    __syncthreads();
    {
        float a = 0.f;
        const float* w = W6 + tid*DM;
        #pragma unroll 8
        for (int k = 0; k < DM; k++) a += s5[k]*w[k];
        out[b*DO + tid] = lrelu(a + b6[tid]);
    }
}

extern "C" void kernel_launch(void* const* d_in, const int* in_sizes, int n_in,
                              void* d_out, int out_size){
    const float* x      = (const float*)d_in[0];
    const float* h      = (const float*)d_in[1];
    const float* conv_w = (const float*)d_in[2];
    const float* conv_b = (const float*)d_in[3];
    const float* bn_g   = (const float*)d_in[4];
    const float* bn_b   = (const float*)d_in[5];
    const float* W1     = (const float*)d_in[6];
    const float* b1     = (const float*)d_in[7];
    const float* W2     = (const float*)d_in[8];
    const float* b2     = (const float*)d_in[9];
    const float* W3     = (const float*)d_in[10];
    const float* b3     = (const float*)d_in[11];
    const float* W4     = (const float*)d_in[12];
    const float* b4     = (const float*)d_in[13];
    const float* W5     = (const float*)d_in[14];
    const float* b5     = (const float*)d_in[15];
    const float* W6     = (const float*)d_in[16];
    const float* b6     = (const float*)d_in[17];
    float* out = (float*)d_out;

    cudaFuncSetAttribute(k_pairs_mma, cudaFuncAttributeMaxDynamicSharedMemorySize, DYN_SMEM);

    k_prep<<<(KC*CC + 255)/256, 256>>>(conv_w, W1);
    k_hw<<<BB, 128>>>(h, W1);
    k_conv<<<dim3(10, BB), 256>>>(x, conv_b);
    k_stats_part<<<40, 256>>>();
    k_stats_fin<<<1, 256>>>(bn_g, bn_b);
    k_uv<<<TOK/8, 256>>>();
    k_pairs_mma<<<GRID_PAIRS, 256, DYN_SMEM>>>(W2, W3, W4, b1, b2, b3, b4);
    k_tail<<<BB, 512>>>(W5, b5, W6, b6, out);
}

// round 8
// speedup vs baseline: 1.1043x; 1.1043x over previous
#include <cuda_runtime.h>
#include <cuda_fp16.h>
#include <math.h>
#include <stdint.h>

#define LL 160
#define BB 16
#define EE 512
#define CC 256
#define HH 512
#define DM 128
#define DO 512
#define TOK (BB*LL)
#define CP 258
#define W1C 1028
#define KC (3*EE)            /* 1536 */
#define SPB 9
#define GRID_PAIRS (BB*SPB)  /* 144 */
#define NKT (KC/16)          /* 96 */

__device__ __half g_whfrag[NKT*32*32*4];
__device__ float g_W1T[CP*256];
__device__ float g_y[TOK*CC];
__device__ float g_ssum[40*256];
__device__ float g_ssq[40*256];
__device__ float g_scale[CC];
__device__ float g_shift[CC];
__device__ float g_u[TOK*DM];
__device__ float g_v[TOK*DM];
__device__ float g_hw[BB*DM];
__device__ float g_part[BB*SPB*DM];

__device__ __forceinline__ float lrelu(float x){ return x > 0.f ? x : 0.1f*x; }

__device__ __forceinline__ uint32_t h2pack(float lo, float hi){
    __half2 h = __floats2half2_rn(lo, hi);
    return *(uint32_t*)&h;
}
__device__ __forceinline__ void mma_f16(float& d0, float& d1, float& d2, float& d3,
                                        uint32_t a0, uint32_t a1, uint32_t a2, uint32_t a3,
                                        uint32_t b0, uint32_t b1){
    asm volatile("mma.sync.aligned.m16n8k16.row.col.f32.f16.f16.f32 "
                 "{%0,%1,%2,%3},{%4,%5,%6,%7},{%8,%9},{%0,%1,%2,%3};"
                 : "+f"(d0), "+f"(d1), "+f"(d2), "+f"(d3)
                 : "r"(a0), "r"(a1), "r"(a2), "r"(a3), "r"(b0), "r"(b1));
}

/* ---------------- prep ---------------- */
__global__ void k_prep(const float* __restrict__ conv_w, const float* __restrict__ W1){
    int idx = blockIdx.x*256 + threadIdx.x;
    if (idx < KC*CC){
        int k = idx >> 8, n = idx & 255;
        int e = k & 511, kk = k >> 9;
        float v = conv_w[n*KC + e*3 + kk];
        int kt = k >> 4, r = k & 15;
        int nt = n >> 3, gg = n & 7, c = (r & 7) >> 1;
        int lane = gg*4 + c;
        int hs = ((r >> 3) << 1) | (r & 1);
        g_whfrag[(((kt*32 + nt)*32 + lane) << 2) + hs] = __float2half(v);
    }
    if (idx < CP*256){
        int k = idx >> 8, n = idx & 255;
        g_W1T[idx] = (n < DM) ? W1[n*W1C + k] : W1[(n-DM)*W1C + CP + k];
    }
}

__global__ void k_hw(const float* __restrict__ h, const float* __restrict__ W1){
    __shared__ float hs[HH];
    int b = blockIdx.x, tid = threadIdx.x;
    for (int i = tid; i < HH; i += 128) hs[i] = h[b*HH + i];
    __syncthreads();
    float acc = 0.f;
    const float* w = W1 + tid*W1C + 2*CP;
    #pragma unroll 8
    for (int c = 0; c < HH; c++) acc += hs[c]*w[c];
    g_hw[b*DM + tid] = acc;
}

/* ---------------- conv1d as fp16 mma GEMM (known-good) ---------------- */
__global__ void __launch_bounds__(256,1) k_conv(const float* __restrict__ x,
                                                const float* __restrict__ conv_b){
    __shared__ uint32_t xh32[18*260];
    __shared__ uint2 wfr[3*32*32];
    int l0 = blockIdx.x*16, b = blockIdx.y;
    int tid = threadIdx.x, w = tid >> 5, t = tid & 31;
    int g = t >> 2, c = t & 3;

    for (int idx = tid; idx < 18*256; idx += 256){
        int r = idx >> 8, i = idx & 255;
        int l = l0 + r - 1;
        uint32_t pv = 0u;
        if (l >= 0 && l < LL){
            const float2 xv = *(const float2*)(x + (l*BB + b)*EE + 2*i);
            pv = h2pack(xv.x, xv.y);
        }
        xh32[r*260 + i] = pv;
    }

    float d[4][4];
    #pragma unroll
    for (int j = 0; j < 4; j++){ d[j][0]=0.f; d[j][1]=0.f; d[j][2]=0.f; d[j][3]=0.f; }

    const uint2* gsrc = (const uint2*)g_whfrag;
    for (int cc = 0; cc < 32; cc++){
        __syncthreads();
        const uint2* src = gsrc + cc*3072;
        #pragma unroll
        for (int q = 0; q < 12; q++) wfr[tid + q*256] = src[tid + q*256];
        __syncthreads();
        #pragma unroll
        for (int kt = 0; kt < 3; kt++){
            int k = cc*48 + kt*16;
            int kk = k >> 9, e2 = (k & 511) >> 1;
            const uint32_t* r0 = xh32 + (g + kk)*260 + e2 + c;
            const uint32_t* r1 = xh32 + (g + 8 + kk)*260 + e2 + c;
            uint32_t a0 = r0[0], a1 = r1[0], a2 = r0[4], a3 = r1[4];
            const uint2* wk = wfr + (kt*32 + w*4)*32 + t;
            #pragma unroll
            for (int j = 0; j < 4; j++){
                uint2 bb = wk[j*32];
                mma_f16(d[j][0], d[j][1], d[j][2], d[j][3], a0, a1, a2, a3, bb.x, bb.y);
            }
        }
    }
    #pragma unroll
    for (int j = 0; j < 4; j++){
        int n = w*32 + j*8 + 2*c;
        float bx = conv_b[n], by = conv_b[n+1];
        int trow = (b*LL + l0 + g)*CC;
        g_y[trow + n]             = lrelu(d[j][0] + bx);
        g_y[trow + n + 1]         = lrelu(d[j][1] + by);
        g_y[trow + 8*CC + n]      = lrelu(d[j][2] + bx);
        g_y[trow + 8*CC + n + 1]  = lrelu(d[j][3] + by);
    }
}

/* BN stats */
__global__ void k_stats_part(){
    int blk = blockIdx.x, tid = threadIdx.x;
    int t0 = blk*64;
    float a = 0.f, q = 0.f;
    for (int tt = 0; tt < 64; tt++){
        float v = g_y[(t0 + tt)*CC + tid];
        a += v; q += v*v;
    }
    g_ssum[blk*256 + tid] = a;
    g_ssq[blk*256 + tid]  = q;
}
__global__ void k_stats_fin(const float* __restrict__ bn_g, const float* __restrict__ bn_b){
    int c = threadIdx.x;
    float a = 0.f, q = 0.f;
    #pragma unroll
    for (int blk = 0; blk < 40; blk++){
        a += g_ssum[blk*256 + c];
        q += g_ssq[blk*256 + c];
    }
    float mu = a/(float)TOK;
    float var = q/(float)TOK - mu*mu;
    float sc = bn_g[c]*rsqrtf(var + 1e-5f);
    g_scale[c] = sc;
    g_shift[c] = bn_b[c] - mu*sc;
}

__global__ void __launch_bounds__(256,4) k_uv(){
    __shared__ float xf[8*260];
    int t0 = blockIdx.x*8;
    int b = t0 / LL;
    int tid = threadIdx.x;
    for (int idx = tid; idx < 8*CC; idx += 256){
        int tok = idx >> 8, c = idx & 255;
        xf[tok*260 + c] = g_y[(t0+tok)*CC + c]*g_scale[c] + g_shift[c];
    }
    if (tid < 16){
        int tok = tid >> 1;
        float fi = (float)(t0 + tok - b*LL);
        float sL = sqrtf(160.f);
        float cv = (tid & 1) ? (fmodf(fi, sL) - 2.f)*0.5f : (fi/sL - 2.f)*0.5f;
        xf[tok*260 + 256 + (tid & 1)] = cv;
    }
    __syncthreads();
    int n = tid;
    float acc[8];
    #pragma unroll
    for (int i = 0; i < 8; i++) acc[i] = 0.f;
    #pragma unroll 2
    for (int k = 0; k < CP; k++){
        float w = g_W1T[k*256 + n];
        #pragma unroll
        for (int tok = 0; tok < 8; tok++) acc[tok] += xf[tok*260 + k]*w;
    }
    if (n < DM){
        #pragma unroll
        for (int tok = 0; tok < 8; tok++) g_u[(t0+tok)*DM + n] = acc[tok];
    } else {
        float hw = g_hw[b*DM + n - DM];
        #pragma unroll
        for (int tok = 0; tok < 8; tok++) g_v[(t0+tok)*DM + n - DM] = acc[tok] + hw;
    }
}

/* ---------------- pair MLP: 256-pair tiles, 2 A-frags/warp share B loads ----
   tile = 16 l x 16 m; warp w covers li = w and li = w+8 (frag 0/1), mi 0..15.
   1 CTA/SM, 256 regs/thread, part_s aliases u_s after the tile loop.       */
#define SM_U     24576
#define SM_V     (SM_U + 16*132)
#define SM_B1    (SM_V + 16*132)
#define SM_BIAS  (SM_B1 + 128)
#define SM_TOTF  (SM_BIAS + 384)
#define DYN_SMEM (SM_TOTF*4)

__global__ void __launch_bounds__(256,1) k_pairs_mma(
        const float* __restrict__ W2, const float* __restrict__ W3, const float* __restrict__ W4,
        const float* __restrict__ b1, const float* __restrict__ b2,
        const float* __restrict__ b3, const float* __restrict__ b4){
    extern __shared__ float smf[];
    float* u_s    = smf + SM_U;
    float* v_s    = smf + SM_V;
    float* b1_s   = smf + SM_B1;
    float* bias_s = smf + SM_BIAS;
    float* part_s = smf + SM_U;      /* alias: live only after the tile loop */
    uint2* wfrag  = (uint2*)smf;

    int tid = threadIdx.x, w = tid >> 5, t = tid & 31;
    int g = t >> 2, c = t & 3;

    for (int l = 0; l < 3; l++){
        const float* W = (l == 0) ? W2 : (l == 1) ? W3 : W4;
        for (int idx = tid; idx < 4096; idx += 256){
            int lane = idx & 31, nt = (idx >> 5) & 15, kt = idx >> 9;
            int gg = lane >> 2, cc = lane & 3;
            const float* Wr = W + (nt*8 + gg)*DM + kt*16 + 2*cc;
            uint2 fr;
            fr.x = h2pack(Wr[0], Wr[1]);
            fr.y = h2pack(Wr[8], Wr[9]);
            wfrag[l*4096 + idx] = fr;
        }
    }
    for (int i = tid; i < 128; i += 256){
        b1_s[i]          = b1[i];
        bias_s[i]        = b2[i];
        bias_s[128 + i]  = b3[i];
        bias_s[256 + i]  = b4[i];
    }

    int cta = blockIdx.x;
    int b = cta / SPB, s = cta % SPB;
    int t0 = s*11 + (s > 0 ? 1 : 0);     /* 100 tiles: s=0 gets 12, others 11 */
    int t1 = t0 + 11 + (s == 0 ? 1 : 0);

    uint32_t a[2][8][4];
    float    d[2][16][4];
    float    acc32[16][2];
    #pragma unroll
    for (int nt = 0; nt < 16; nt++){ acc32[nt][0] = 0.f; acc32[nt][1] = 0.f; }

    for (int tt = t0; tt < t1; tt++){
        int lt0 = (tt / 10)*16, m0 = (tt % 10)*16;
        __syncthreads();
        for (int idx = tid; idx < 16*DM; idx += 256){
            int mi = idx >> 7, k = idx & 127;
            u_s[mi*132 + k] = g_u[(b*LL + m0 + mi)*DM + k];
        }
        for (int idx = tid; idx < 16*DM; idx += 256){
            int li = idx >> 7, k = idx & 127;
            v_s[li*132 + k] = g_v[(b*LL + lt0 + li)*DM + k];
        }
        __syncthreads();

        /* layer-1 activation fragments: frag f -> li = w + 8f */
        #pragma unroll
        for (int f = 0; f < 2; f++){
            const float* vrow = v_s + (w + 8*f)*132;
            #pragma unroll
            for (int kt = 0; kt < 8; kt++){
                int k = kt*16 + 2*c;
                const float* vr = vrow + k;
                const float* br = b1_s + k;
                float vb0 = vr[0] + br[0], vb1 = vr[1] + br[1];
                float vb8 = vr[8] + br[8], vb9 = vr[9] + br[9];
                const float* ug = u_s + g*132 + k;
                const float* uh = u_s + (g+8)*132 + k;
                a[f][kt][0] = h2pack(lrelu(ug[0] + vb0), lrelu(ug[1] + vb1));
                a[f][kt][1] = h2pack(lrelu(uh[0] + vb0), lrelu(uh[1] + vb1));
                a[f][kt][2] = h2pack(lrelu(ug[8] + vb8), lrelu(ug[9] + vb9));
                a[f][kt][3] = h2pack(lrelu(uh[8] + vb8), lrelu(uh[9] + vb9));
            }
        }

        #pragma unroll 1
        for (int l = 0; l < 3; l++){
            #pragma unroll
            for (int nt = 0; nt < 16; nt++){
                d[0][nt][0]=0.f; d[0][nt][1]=0.f; d[0][nt][2]=0.f; d[0][nt][3]=0.f;
                d[1][nt][0]=0.f; d[1][nt][1]=0.f; d[1][nt][2]=0.f; d[1][nt][3]=0.f;
            }
            const uint2* wl = wfrag + l*4096 + t;
            #pragma unroll
            for (int kt = 0; kt < 8; kt++){
                const uint2* wk = wl + kt*512;
                #pragma unroll
                for (int nt = 0; nt < 16; nt++){
                    uint2 bb = wk[nt*32];     /* one LDS.64 feeds two mma */
                    mma_f16(d[0][nt][0], d[0][nt][1], d[0][nt][2], d[0][nt][3],
                            a[0][kt][0], a[0][kt][1], a[0][kt][2], a[0][kt][3], bb.x, bb.y);
                    mma_f16(d[1][nt][0], d[1][nt][1], d[1][nt][2], d[1][nt][3],
                            a[1][kt][0], a[1][kt][1], a[1][kt][2], a[1][kt][3], bb.x, bb.y);
                }
            }
            if (l < 2){
                const float* bl = bias_s + l*128;
                #pragma unroll
                for (int f = 0; f < 2; f++){
                    #pragma unroll
                    for (int kt = 0; kt < 8; kt++){
                        float bx0 = bl[kt*16 + 2*c],     by0 = bl[kt*16 + 2*c + 1];
                        float bx8 = bl[kt*16 + 2*c + 8], by8 = bl[kt*16 + 2*c + 9];
                        a[f][kt][0] = h2pack(lrelu(d[f][2*kt][0]   + bx0), lrelu(d[f][2*kt][1]   + by0));
                        a[f][kt][1] = h2pack(lrelu(d[f][2*kt][2]   + bx0), lrelu(d[f][2*kt][3]   + by0));
                        a[f][kt][2] = h2pack(lrelu(d[f][2*kt+1][0] + bx8), lrelu(d[f][2*kt+1][1] + by8));
                        a[f][kt][3] = h2pack(lrelu(d[f][2*kt+1][2] + bx8), lrelu(d[f][2*kt+1][3] + by8));
                    }
                }
            } else {
                const float* bl = bias_s + 256;
                #pragma unroll
                for (int nt = 0; nt < 16; nt++){
                    float bx = bl[nt*8 + 2*c], by = bl[nt*8 + 2*c + 1];
                    acc32[nt][0] += lrelu(d[0][nt][0] + bx) + lrelu(d[0][nt][2] + bx)
                                  + lrelu(d[1][nt][0] + bx) + lrelu(d[1][nt][2] + bx);
                    acc32[nt][1] += lrelu(d[0][nt][1] + by) + lrelu(d[0][nt][3] + by)
                                  + lrelu(d[1][nt][1] + by) + lrelu(d[1][nt][3] + by);
                }
            }
        }
    }

    __syncthreads();   /* fence before part_s aliases u_s */

    #pragma unroll
    for (int nt = 0; nt < 16; nt++){
        #pragma unroll
        for (int r = 0; r < 2; r++){
            float v = acc32[nt][r];
            v += __shfl_xor_sync(0xffffffffu, v, 4);
            v += __shfl_xor_sync(0xffffffffu, v, 8);
            v += __shfl_xor_sync(0xffffffffu, v, 16);
            acc32[nt][r] = v;
        }
    }
    if (g == 0){
        #pragma unroll
        for (int nt = 0; nt < 16; nt++){
            part_s[w*128 + nt*8 + 2*c]     = acc32[nt][0];
            part_s[w*128 + nt*8 + 2*c + 1] = acc32[nt][1];
        }
    }
    __syncthreads();
    if (tid < 128){
        float r = 0.f;
        #pragma unroll
        for (int ww = 0; ww < 8; ww++) r += part_s[ww*128 + tid];
        g_part[(b*SPB + s)*DM + tid] = r;
    }
}

/* final reduction + 2-layer head */
__global__ void k_tail(const float* __restrict__ W5, const float* __restrict__ b5,
                       const float* __restrict__ W6, const float* __restrict__ b6,
                       float* __restrict__ out){
    __shared__ float s_s[DM], s5[DM];
    int b = blockIdx.x, tid = threadIdx.x;
    if (tid < DM){
        float a = 0.f;
        #pragma unroll
        for (int t = 0; t < SPB; t++) a += g_part[(b*SPB + t)*DM + tid];
        s_s[tid] = a;
    }
    __syncthreads();
    if (tid < DM){
        float a = 0.f;
        const float* w = W5 + tid*DM;
        #pragma unroll 8
        for (int k = 0; k < DM; k++) a += s_s[k]*w[k];
        s5[tid] = lrelu(a + b5[tid]);
    }
    __syncthreads();
    {
        float a = 0.f;
        const float* w = W6 + tid*DM;
        #pragma unroll 8
        for (int k = 0; k < DM; k++) a += s5[k]*w[k];
        out[b*DO + tid] = lrelu(a + b6[tid]);
    }
}

extern "C" void kernel_launch(void* const* d_in, const int* in_sizes, int n_in,
                              void* d_out, int out_size){
    const float* x      = (const float*)d_in[0];
    const float* h      = (const float*)d_in[1];
    const float* conv_w = (const float*)d_in[2];
    const float* conv_b = (const float*)d_in[3];
    const float* bn_g   = (const float*)d_in[4];
    const float* bn_b   = (const float*)d_in[5];
    const float* W1     = (const float*)d_in[6];
    const float* b1     = (const float*)d_in[7];
    const float* W2     = (const float*)d_in[8];
    const float* b2     = (const float*)d_in[9];
    const float* W3     = (const float*)d_in[10];
    const float* b3     = (const float*)d_in[11];
    const float* W4     = (const float*)d_in[12];
    const float* b4     = (const float*)d_in[13];
    const float* W5     = (const float*)d_in[14];
    const float* b5     = (const float*)d_in[15];
    const float* W6     = (const float*)d_in[16];
    const float* b6     = (const float*)d_in[17];
    float* out = (float*)d_out;

    cudaFuncSetAttribute(k_pairs_mma, cudaFuncAttributeMaxDynamicSharedMemorySize, DYN_SMEM);

    k_prep<<<(KC*CC + 255)/256, 256>>>(conv_w, W1);
    k_hw<<<BB, 128>>>(h, W1);
    k_conv<<<dim3(10, BB), 256>>>(x, conv_b);
    k_stats_part<<<40, 256>>>();
    k_stats_fin<<<1, 256>>>(bn_g, bn_b);
    k_uv<<<TOK/8, 256>>>();
    k_pairs_mma<<<GRID_PAIRS, 256, DYN_SMEM>>>(W2, W3, W4, b1, b2, b3, b4);
    k_tail<<<BB, 512>>>(W5, b5, W6, b6, out);
}

// round 9
// speedup vs baseline: 1.1327x; 1.0257x over previous
#include <cuda_runtime.h>
#include <cuda_fp16.h>
#include <math.h>
#include <stdint.h>

#define LL 160
#define BB 16
#define EE 512
#define CC 256
#define HH 512
#define DM 128
#define DO 512
#define TOK (BB*LL)
#define CP 258
#define W1C 1028
#define KC (3*EE)            /* 1536 */
#define SPB 9
#define GRID_PAIRS (BB*SPB)  /* 144 */
#define NKT (KC/16)          /* 96 */

__device__ __half g_whfrag[NKT*32*32*4];
__device__ float g_W1T[CP*256];
__device__ float g_y[TOK*CC];
__device__ float g_ssum[40*256];
__device__ float g_ssq[40*256];
__device__ float g_scale[CC];
__device__ float g_shift[CC];
__device__ float g_u[TOK*DM];
__device__ float g_v[TOK*DM];
__device__ float g_hw[BB*DM];
__device__ float g_part[BB*SPB*DM];

__device__ __forceinline__ float lrelu(float x){ return x > 0.f ? x : 0.1f*x; }

__device__ __forceinline__ uint32_t h2pack(float lo, float hi){
    __half2 h = __floats2half2_rn(lo, hi);
    return *(uint32_t*)&h;
}
__device__ __forceinline__ void mma_f16(float& d0, float& d1, float& d2, float& d3,
                                        uint32_t a0, uint32_t a1, uint32_t a2, uint32_t a3,
                                        uint32_t b0, uint32_t b1){
    asm volatile("mma.sync.aligned.m16n8k16.row.col.f32.f16.f16.f32 "
                 "{%0,%1,%2,%3},{%4,%5,%6,%7},{%8,%9},{%0,%1,%2,%3};"
                 : "+f"(d0), "+f"(d1), "+f"(d2), "+f"(d3)
                 : "r"(a0), "r"(a1), "r"(a2), "r"(a3), "r"(b0), "r"(b1));
}

/* ---------------- prep (+ fused h-projection in blocks 0..15) ---------------- */
__global__ void k_prep(const float* __restrict__ conv_w, const float* __restrict__ W1,
                       const float* __restrict__ h){
    __shared__ float hs[HH];
    __shared__ float hp[256];
    int tid = threadIdx.x;
    int idx = blockIdx.x*256 + tid;
    if (idx < KC*CC){
        int k = idx >> 8, n = idx & 255;
        int e = k & 511, kk = k >> 9;
        float v = conv_w[n*KC + e*3 + kk];
        int kt = k >> 4, r = k & 15;
        int nt = n >> 3, gg = n & 7, c = (r & 7) >> 1;
        int lane = gg*4 + c;
        int hsl = ((r >> 3) << 1) | (r & 1);
        g_whfrag[(((kt*32 + nt)*32 + lane) << 2) + hsl] = __float2half(v);
    }
    if (idx < CP*256){
        int k = idx >> 8, n = idx & 255;
        g_W1T[idx] = (n < DM) ? W1[n*W1C + k] : W1[(n-DM)*W1C + CP + k];
    }
    if (blockIdx.x < BB){
        int b = blockIdx.x;
        for (int i = tid; i < HH; i += 256) hs[i] = h[b*HH + i];
        __syncthreads();
        int d = tid & 127, half = tid >> 7;
        const float* w = W1 + d*W1C + 2*CP + half*256;
        float acc = 0.f;
        #pragma unroll 8
        for (int c = 0; c < 256; c++) acc += hs[half*256 + c]*w[c];
        hp[tid] = acc;
        __syncthreads();
        if (tid < 128) g_hw[b*DM + tid] = hp[tid] + hp[tid + 128];
    }
}

/* ---------------- conv1d as fp16 mma GEMM (known-good) ---------------- */
__global__ void __launch_bounds__(256,1) k_conv(const float* __restrict__ x,
                                                const float* __restrict__ conv_b){
    __shared__ uint32_t xh32[18*260];
    __shared__ uint2 wfr[3*32*32];
    int l0 = blockIdx.x*16, b = blockIdx.y;
    int tid = threadIdx.x, w = tid >> 5, t = tid & 31;
    int g = t >> 2, c = t & 3;

    for (int idx = tid; idx < 18*256; idx += 256){
        int r = idx >> 8, i = idx & 255;
        int l = l0 + r - 1;
        uint32_t pv = 0u;
        if (l >= 0 && l < LL){
            const float2 xv = *(const float2*)(x + (l*BB + b)*EE + 2*i);
            pv = h2pack(xv.x, xv.y);
        }
        xh32[r*260 + i] = pv;
    }

    float d[4][4];
    #pragma unroll
    for (int j = 0; j < 4; j++){ d[j][0]=0.f; d[j][1]=0.f; d[j][2]=0.f; d[j][3]=0.f; }

    const uint2* gsrc = (const uint2*)g_whfrag;
    for (int cc = 0; cc < 32; cc++){
        __syncthreads();
        const uint2* src = gsrc + cc*3072;
        #pragma unroll
        for (int q = 0; q < 12; q++) wfr[tid + q*256] = src[tid + q*256];
        __syncthreads();
        #pragma unroll
        for (int kt = 0; kt < 3; kt++){
            int k = cc*48 + kt*16;
            int kk = k >> 9, e2 = (k & 511) >> 1;
            const uint32_t* r0 = xh32 + (g + kk)*260 + e2 + c;
            const uint32_t* r1 = xh32 + (g + 8 + kk)*260 + e2 + c;
            uint32_t a0 = r0[0], a1 = r1[0], a2 = r0[4], a3 = r1[4];
            const uint2* wk = wfr + (kt*32 + w*4)*32 + t;
            #pragma unroll
            for (int j = 0; j < 4; j++){
                uint2 bb = wk[j*32];
                mma_f16(d[j][0], d[j][1], d[j][2], d[j][3], a0, a1, a2, a3, bb.x, bb.y);
            }
        }
    }
    #pragma unroll
    for (int j = 0; j < 4; j++){
        int n = w*32 + j*8 + 2*c;
        float bx = conv_b[n], by = conv_b[n+1];
        int trow = (b*LL + l0 + g)*CC;
        g_y[trow + n]             = lrelu(d[j][0] + bx);
        g_y[trow + n + 1]         = lrelu(d[j][1] + by);
        g_y[trow + 8*CC + n]      = lrelu(d[j][2] + bx);
        g_y[trow + 8*CC + n + 1]  = lrelu(d[j][3] + by);
    }
}

/* BN stats */
__global__ void k_stats_part(){
    int blk = blockIdx.x, tid = threadIdx.x;
    int t0 = blk*64;
    float a = 0.f, q = 0.f;
    for (int tt = 0; tt < 64; tt++){
        float v = g_y[(t0 + tt)*CC + tid];
        a += v; q += v*v;
    }
    g_ssum[blk*256 + tid] = a;
    g_ssq[blk*256 + tid]  = q;
}
__global__ void k_stats_fin(const float* __restrict__ bn_g, const float* __restrict__ bn_b){
    int c = threadIdx.x;
    float a = 0.f, q = 0.f;
    #pragma unroll
    for (int blk = 0; blk < 40; blk++){
        a += g_ssum[blk*256 + c];
        q += g_ssq[blk*256 + c];
    }
    float mu = a/(float)TOK;
    float var = q/(float)TOK - mu*mu;
    float sc = bn_g[c]*rsqrtf(var + 1e-5f);
    g_scale[c] = sc;
    g_shift[c] = bn_b[c] - mu*sc;
}

__global__ void __launch_bounds__(256,4) k_uv(){
    __shared__ float xf[8*260];
    int t0 = blockIdx.x*8;
    int b = t0 / LL;
    int tid = threadIdx.x;
    for (int idx = tid; idx < 8*CC; idx += 256){
        int tok = idx >> 8, c = idx & 255;
        xf[tok*260 + c] = g_y[(t0+tok)*CC + c]*g_scale[c] + g_shift[c];
    }
    if (tid < 16){
        int tok = tid >> 1;
        float fi = (float)(t0 + tok - b*LL);
        float sL = sqrtf(160.f);
        float cv = (tid & 1) ? (fmodf(fi, sL) - 2.f)*0.5f : (fi/sL - 2.f)*0.5f;
        xf[tok*260 + 256 + (tid & 1)] = cv;
    }
    __syncthreads();
    int n = tid;
    float acc[8];
    #pragma unroll
    for (int i = 0; i < 8; i++) acc[i] = 0.f;
    #pragma unroll 2
    for (int k = 0; k < CP; k++){
        float w = g_W1T[k*256 + n];
        #pragma unroll
        for (int tok = 0; tok < 8; tok++) acc[tok] += xf[tok*260 + k]*w;
    }
    if (n < DM){
        #pragma unroll
        for (int tok = 0; tok < 8; tok++) g_u[(t0+tok)*DM + n] = acc[tok];
    } else {
        float hw = g_hw[b*DM + n - DM];
        #pragma unroll
        for (int tok = 0; tok < 8; tok++) g_v[(t0+tok)*DM + n - DM] = acc[tok] + hw;
    }
}

/* ---------------- pair MLP: 256-pair tiles, nt-split halves (no spills) ---- */
#define SM_U     24576
#define SM_V     (SM_U + 16*132)
#define SM_B1    (SM_V + 16*132)
#define SM_BIAS  (SM_B1 + 128)
#define SM_TOTF  (SM_BIAS + 384)
#define DYN_SMEM (SM_TOTF*4)

__global__ void __launch_bounds__(256,1) k_pairs_mma(
        const float* __restrict__ W2, const float* __restrict__ W3, const float* __restrict__ W4,
        const float* __restrict__ b1, const float* __restrict__ b2,
        const float* __restrict__ b3, const float* __restrict__ b4){
    extern __shared__ float smf[];
    float* u_s    = smf + SM_U;
    float* v_s    = smf + SM_V;
    float* b1_s   = smf + SM_B1;
    float* bias_s = smf + SM_BIAS;
    float* part_s = smf + SM_U;      /* alias: live only after the tile loop */
    uint2* wfrag  = (uint2*)smf;

    int tid = threadIdx.x, w = tid >> 5, t = tid & 31;
    int g = t >> 2, c = t & 3;

    for (int l = 0; l < 3; l++){
        const float* W = (l == 0) ? W2 : (l == 1) ? W3 : W4;
        for (int idx = tid; idx < 4096; idx += 256){
            int lane = idx & 31, nt = (idx >> 5) & 15, kt = idx >> 9;
            int gg = lane >> 2, cc = lane & 3;
            const float* Wr = W + (nt*8 + gg)*DM + kt*16 + 2*cc;
            uint2 fr;
            fr.x = h2pack(Wr[0], Wr[1]);
            fr.y = h2pack(Wr[8], Wr[9]);
            wfrag[l*4096 + idx] = fr;
        }
    }
    for (int i = tid; i < 128; i += 256){
        b1_s[i]          = b1[i];
        bias_s[i]        = b2[i];
        bias_s[128 + i]  = b3[i];
        bias_s[256 + i]  = b4[i];
    }

    int cta = blockIdx.x;
    int b = cta / SPB, s = cta % SPB;
    int t0 = s*11 + (s > 0 ? 1 : 0);
    int t1 = t0 + 11 + (s == 0 ? 1 : 0);

    uint32_t a[2][8][4];
    uint32_t an[2][4][4];
    float    d[2][8][4];
    float    acc32[16][2];
    #pragma unroll
    for (int nt = 0; nt < 16; nt++){ acc32[nt][0] = 0.f; acc32[nt][1] = 0.f; }

    for (int tt = t0; tt < t1; tt++){
        int lt0 = (tt / 10)*16, m0 = (tt % 10)*16;
        __syncthreads();
        for (int idx = tid; idx < 16*DM; idx += 256){
            int mi = idx >> 7, k = idx & 127;
            u_s[mi*132 + k] = g_u[(b*LL + m0 + mi)*DM + k];
        }
        for (int idx = tid; idx < 16*DM; idx += 256){
            int li = idx >> 7, k = idx & 127;
            v_s[li*132 + k] = g_v[(b*LL + lt0 + li)*DM + k];
        }
        __syncthreads();

        #pragma unroll
        for (int f = 0; f < 2; f++){
            const float* vrow = v_s + (w + 8*f)*132;
            #pragma unroll
            for (int kt = 0; kt < 8; kt++){
                int k = kt*16 + 2*c;
                const float* vr = vrow + k;
                const float* br = b1_s + k;
                float vb0 = vr[0] + br[0], vb1 = vr[1] + br[1];
                float vb8 = vr[8] + br[8], vb9 = vr[9] + br[9];
                const float* ug = u_s + g*132 + k;
                const float* uh = u_s + (g+8)*132 + k;
                a[f][kt][0] = h2pack(lrelu(ug[0] + vb0), lrelu(ug[1] + vb1));
                a[f][kt][1] = h2pack(lrelu(uh[0] + vb0), lrelu(uh[1] + vb1));
                a[f][kt][2] = h2pack(lrelu(ug[8] + vb8), lrelu(ug[9] + vb9));
                a[f][kt][3] = h2pack(lrelu(uh[8] + vb8), lrelu(uh[9] + vb9));
            }
        }

        #pragma unroll 1
        for (int l = 0; l < 3; l++){
            #pragma unroll
            for (int h = 0; h < 2; h++){
                #pragma unroll
                for (int ntl = 0; ntl < 8; ntl++){
                    d[0][ntl][0]=0.f; d[0][ntl][1]=0.f; d[0][ntl][2]=0.f; d[0][ntl][3]=0.f;
                    d[1][ntl][0]=0.f; d[1][ntl][1]=0.f; d[1][ntl][2]=0.f; d[1][ntl][3]=0.f;
                }
                const uint2* wl = wfrag + l*4096 + h*256 + t;
                #pragma unroll
                for (int kt = 0; kt < 8; kt++){
                    const uint2* wk = wl + kt*512;
                    #pragma unroll
                    for (int ntl = 0; ntl < 8; ntl++){
                        uint2 bb = wk[ntl*32];
                        mma_f16(d[0][ntl][0], d[0][ntl][1], d[0][ntl][2], d[0][ntl][3],
                                a[0][kt][0], a[0][kt][1], a[0][kt][2], a[0][kt][3], bb.x, bb.y);
                        mma_f16(d[1][ntl][0], d[1][ntl][1], d[1][ntl][2], d[1][ntl][3],
                                a[1][kt][0], a[1][kt][1], a[1][kt][2], a[1][kt][3], bb.x, bb.y);
                    }
                }
                if (l < 2){
                    const float* bl = bias_s + l*128 + h*64;
                    #pragma unroll
                    for (int f = 0; f < 2; f++){
                        #pragma unroll
                        for (int ktl = 0; ktl < 4; ktl++){
                            float bx0 = bl[ktl*16 + 2*c],     by0 = bl[ktl*16 + 2*c + 1];
                            float bx8 = bl[ktl*16 + 2*c + 8], by8 = bl[ktl*16 + 2*c + 9];
                            uint32_t u0 = h2pack(lrelu(d[f][2*ktl][0]   + bx0), lrelu(d[f][2*ktl][1]   + by0));
                            uint32_t u1 = h2pack(lrelu(d[f][2*ktl][2]   + bx0), lrelu(d[f][2*ktl][3]   + by0));
                            uint32_t u2 = h2pack(lrelu(d[f][2*ktl+1][0] + bx8), lrelu(d[f][2*ktl+1][1] + by8));
                            uint32_t u3 = h2pack(lrelu(d[f][2*ktl+1][2] + bx8), lrelu(d[f][2*ktl+1][3] + by8));
                            if (h == 0){
                                an[f][ktl][0]=u0; an[f][ktl][1]=u1; an[f][ktl][2]=u2; an[f][ktl][3]=u3;
                            } else {
                                a[f][4+ktl][0]=u0; a[f][4+ktl][1]=u1; a[f][4+ktl][2]=u2; a[f][4+ktl][3]=u3;
                            }
                        }
                    }
                    if (h == 1){
                        #pragma unroll
                        for (int f = 0; f < 2; f++)
                            #pragma unroll
                            for (int ktl = 0; ktl < 4; ktl++){
                                a[f][ktl][0]=an[f][ktl][0]; a[f][ktl][1]=an[f][ktl][1];
                                a[f][ktl][2]=an[f][ktl][2]; a[f][ktl][3]=an[f][ktl][3];
                            }
                    }
                } else {
                    const float* bl = bias_s + 256 + h*64;
                    #pragma unroll
                    for (int ntl = 0; ntl < 8; ntl++){
                        int nt = 8*h + ntl;
                        float bx = bl[ntl*8 + 2*c], by = bl[ntl*8 + 2*c + 1];
                        acc32[nt][0] += lrelu(d[0][ntl][0] + bx) + lrelu(d[0][ntl][2] + bx)
                                      + lrelu(d[1][ntl][0] + bx) + lrelu(d[1][ntl][2] + bx);
                        acc32[nt][1] += lrelu(d[0][ntl][1] + by) + lrelu(d[0][ntl][3] + by)
                                      + lrelu(d[1][ntl][1] + by) + lrelu(d[1][ntl][3] + by);
                    }
                }
            }
        }
    }

    __syncthreads();   /* fence before part_s aliases u_s */

    #pragma unroll
    for (int nt = 0; nt < 16; nt++){
        #pragma unroll
        for (int r = 0; r < 2; r++){
            float v = acc32[nt][r];
            v += __shfl_xor_sync(0xffffffffu, v, 4);
            v += __shfl_xor_sync(0xffffffffu, v, 8);
            v += __shfl_xor_sync(0xffffffffu, v, 16);
            acc32[nt][r] = v;
        }
    }
    if (g == 0){
        #pragma unroll
        for (int nt = 0; nt < 16; nt++){
            part_s[w*128 + nt*8 + 2*c]     = acc32[nt][0];
            part_s[w*128 + nt*8 + 2*c + 1] = acc32[nt][1];
        }
    }
    __syncthreads();
    if (tid < 128){
        float r = 0.f;
        #pragma unroll
        for (int ww = 0; ww < 8; ww++) r += part_s[ww*128 + tid];
        g_part[(b*SPB + s)*DM + tid] = r;
    }
}

/* final reduction + 2-layer head */
__global__ void k_tail(const float* __restrict__ W5, const float* __restrict__ b5,
                       const float* __restrict__ W6, const float* __restrict__ b6,
                       float* __restrict__ out){
    __shared__ float s_s[DM], s5[DM];
    int b = blockIdx.x, tid = threadIdx.x;
    if (tid < DM){
        float a = 0.f;
        #pragma unroll
        for (int t = 0; t < SPB; t++) a += g_part[(b*SPB + t)*DM + tid];
        s_s[tid] = a;
    }
    __syncthreads();
    if (tid < DM){
        float a = 0.f;
        const float* w = W5 + tid*DM;
        #pragma unroll 8
        for (int k = 0; k < DM; k++) a += s_s[k]*w[k];
        s5[tid] = lrelu(a + b5[tid]);
    }
    __syncthreads();
    {
        float a = 0.f;
        const float* w = W6 + tid*DM;
        #pragma unroll 8
        for (int k = 0; k < DM; k++) a += s5[k]*w[k];
        out[b*DO + tid] = lrelu(a + b6[tid]);
    }
}

extern "C" void kernel_launch(void* const* d_in, const int* in_sizes, int n_in,
                              void* d_out, int out_size){
    const float* x      = (const float*)d_in[0];
    const float* h      = (const float*)d_in[1];
    const float* conv_w = (const float*)d_in[2];
    const float* conv_b = (const float*)d_in[3];
    const float* bn_g   = (const float*)d_in[4];
    const float* bn_b   = (const float*)d_in[5];
    const float* W1     = (const float*)d_in[6];
    const float* b1     = (const float*)d_in[7];
    const float* W2     = (const float*)d_in[8];
    const float* b2     = (const float*)d_in[9];
    const float* W3     = (const float*)d_in[10];
    const float* b3     = (const float*)d_in[11];
    const float* W4     = (const float*)d_in[12];
    const float* b4     = (const float*)d_in[13];
    const float* W5     = (const float*)d_in[14];
    const float* b5     = (const float*)d_in[15];
    const float* W6     = (const float*)d_in[16];
    const float* b6     = (const float*)d_in[17];
    float* out = (float*)d_out;

    cudaFuncSetAttribute(k_pairs_mma, cudaFuncAttributeMaxDynamicSharedMemorySize, DYN_SMEM);

    k_prep<<<(KC*CC + 255)/256, 256>>>(conv_w, W1, h);   /* 1 */
    k_conv<<<dim3(10, BB), 256>>>(x, conv_b);            /* 2 */
    k_stats_part<<<40, 256>>>();                         /* 3 */
    k_stats_fin<<<1, 256>>>(bn_g, bn_b);                 /* 4 */
    k_uv<<<TOK/8, 256>>>();                              /* 5 */
    k_pairs_mma<<<GRID_PAIRS, 256, DYN_SMEM>>>(W2, W3, W4, b1, b2, b3, b4);  /* 6: profiled */
    k_tail<<<BB, 512>>>(W5, b5, W6, b6, out);            /* 7 */
}